// round 6
// baseline (speedup 1.0000x reference)
#include <cuda_runtime.h>
#include <cstdint>
#include <cstddef>

// ---------------------------------------------------------------------------
// Problem dims (fixed)
// ---------------------------------------------------------------------------
static constexpr int M_DIM = 2048;
static constexpr int K_DIM = 4096;
static constexpr int N_DIM = 4096;
static constexpr int KB    = K_DIM / 128;     // 32 k-blocks of 128

// GEMM tiling
static constexpr int BM = 128;
static constexpr int BN = 128;
static constexpr int BK = 64;                 // bytes (int8) per chunk
static constexpr int NCHUNKS = K_DIM / BK;    // 64
static constexpr int STAGES  = 4;
static constexpr int ROWB    = 80;            // 64 data + 16 pad: conflict-free frags
static constexpr int A_STAGE = BM * ROWB;     // 10240
static constexpr int B_STAGE = BN * ROWB;     // 10240
static constexpr int STAGE_BYTES = A_STAGE + B_STAGE;            // 20480

// SMEM layout
static constexpr int XS_STRIDE = 33;                             // padded floats
static constexpr int OFF_XS  = 0;                                // 128*33*4 = 16896
static constexpr int OFF_WS  = 16896;                            // 32 floats
static constexpr int OFF_STG = 17408;
static constexpr int SMEM_BYTES = OFF_STG + STAGES * STAGE_BYTES; // 99328

// Scratch (allocation-free rule: __device__ globals)
__device__ __align__(1024) int8_t g_Aq[(size_t)M_DIM * K_DIM];  // 8 MB
__device__ __align__(1024) int8_t g_Wq[(size_t)N_DIM * K_DIM];  // 16 MB
__device__ __align__(256)  float  g_xs[(size_t)M_DIM * KB];     // 256 KB
__device__ int g_wfmt;   // 0=int8, 1=int32, 2=float32

// ---------------------------------------------------------------------------
// Helpers
// ---------------------------------------------------------------------------
__device__ __forceinline__ uint32_t smem_u32(const void* p) {
    uint32_t a;
    asm("{ .reg .u64 t; cvta.to.shared.u64 t, %1; cvt.u32.u64 %0, t; }"
        : "=r"(a) : "l"(p));
    return a;
}

__device__ __forceinline__ void cp_async16(uint32_t dst, const void* src) {
    asm volatile("cp.async.cg.shared.global [%0], [%1], 16;" :: "r"(dst), "l"(src));
}

__device__ __forceinline__ uint32_t lds32(uint32_t addr) {
    uint32_t v;
    asm volatile("ld.shared.b32 %0, [%1];" : "=r"(v) : "r"(addr));
    return v;
}

__device__ __forceinline__ void mma_s8(int32_t* c, const uint32_t* a,
                                       uint32_t b0, uint32_t b1) {
    asm volatile(
        "mma.sync.aligned.m16n8k32.row.col.s32.s8.s8.s32 "
        "{%0,%1,%2,%3}, {%4,%5,%6,%7}, {%8,%9}, {%0,%1,%2,%3};"
        : "+r"(c[0]), "+r"(c[1]), "+r"(c[2]), "+r"(c[3])
        : "r"(a[0]), "r"(a[1]), "r"(a[2]), "r"(a[3]), "r"(b0), "r"(b1));
}

// ---------------------------------------------------------------------------
// Kernel 0a: detect the storage format of w_q (harness may promote int8).
// Deterministic: pure function of input bytes.
// ---------------------------------------------------------------------------
__global__ void detect_w_kernel(const uint32_t* __restrict__ w) {
    __shared__ int s_int, s_flt;
    if (threadIdx.x == 0) { s_int = 1; s_flt = 1; }
    __syncthreads();
    int ok_int = 1, ok_flt = 1;
    for (int i = threadIdx.x; i < 4096; i += 256) {
        uint32_t u = w[i];
        int v = (int)u;
        if (v < -127 || v > 127) ok_int = 0;
        float f = __uint_as_float(u);
        if (!(fabsf(f) <= 127.0f && rintf(f) == f)) ok_flt = 0;
    }
    if (!ok_int) atomicAnd(&s_int, 0);
    if (!ok_flt) atomicAnd(&s_flt, 0);
    __syncthreads();
    if (threadIdx.x == 0) g_wfmt = s_int ? 1 : (s_flt ? 2 : 0);
}

// ---------------------------------------------------------------------------
// Kernel 0b: canonicalize w_q into int8 g_Wq from whichever format.
// 4 elements per thread.
// ---------------------------------------------------------------------------
__global__ void __launch_bounds__(256) convert_w_kernel(const void* __restrict__ wsrc) {
    const int fmt = g_wfmt;
    size_t t = (size_t)blockIdx.x * 256 + threadIdx.x;   // 0 .. N*K/4-1
    char4 q;
    if (fmt == 1) {
        int4 v = reinterpret_cast<const int4*>(wsrc)[t];
        q = make_char4((char)v.x, (char)v.y, (char)v.z, (char)v.w);
    } else if (fmt == 2) {
        float4 v = reinterpret_cast<const float4*>(wsrc)[t];
        q = make_char4((char)(int)v.x, (char)(int)v.y,
                       (char)(int)v.z, (char)(int)v.w);
    } else {
        q = reinterpret_cast<const char4*>(wsrc)[t];
    }
    reinterpret_cast<char4*>(g_Wq)[t] = q;
}

// ---------------------------------------------------------------------------
// Kernel 1: per-(row, 128-block) int8 quantization of x (matches jnp exactly)
// one warp per (m, kb)
// ---------------------------------------------------------------------------
__global__ void __launch_bounds__(256) quant_x_kernel(const float* __restrict__ x) {
    int warp = (blockIdx.x * blockDim.x + threadIdx.x) >> 5;
    int lane = threadIdx.x & 31;
    int m  = warp >> 5;      // KB = 32 blocks per row
    int kb = warp & 31;

    const float4* xp = reinterpret_cast<const float4*>(x + (size_t)m * K_DIM + kb * 128);
    float4 v = xp[lane];
    float a = fmaxf(fmaxf(fabsf(v.x), fabsf(v.y)), fmaxf(fabsf(v.z), fabsf(v.w)));
    #pragma unroll
    for (int o = 16; o; o >>= 1) a = fmaxf(a, __shfl_xor_sync(0xffffffffu, a, o));
    float s = fmaxf(a, 1e-8f) * (1.0f / 127.0f);

    // round-half-even + clip, identical to jnp.clip(jnp.round(x/s), -127, 127)
    char4 q;
    q.x = (char)(int)fminf(fmaxf(rintf(__fdiv_rn(v.x, s)), -127.f), 127.f);
    q.y = (char)(int)fminf(fmaxf(rintf(__fdiv_rn(v.y, s)), -127.f), 127.f);
    q.z = (char)(int)fminf(fmaxf(rintf(__fdiv_rn(v.z, s)), -127.f), 127.f);
    q.w = (char)(int)fminf(fmaxf(rintf(__fdiv_rn(v.w, s)), -127.f), 127.f);
    reinterpret_cast<char4*>(g_Aq + (size_t)m * K_DIM + kb * 128)[lane] = q;
    if (lane == 0) g_xs[(size_t)m * KB + kb] = s;
}

// ---------------------------------------------------------------------------
// Kernel 2: int8 GEMM with blockwise fp32 rescale + bias
// y[m,n] = sum_c xs[m,c]*ws[n/128,c]*(sum_{k in block c} qx*qw) + bias[n]
// CTA: 128x128, 512 thr (16 warps, 4x4), 4-stage cp.async pipeline.
// Fragment loads: lds.b32 at PTX-ISA fragment-table addresses
// (80B row stride -> provably conflict-free).
// ---------------------------------------------------------------------------
__device__ __forceinline__ void load_chunk(uint32_t sbase, int stage, int c,
                                           int m0, int n0, int tid) {
    uint32_t sa = sbase + OFF_STG + stage * STAGE_BYTES;
    uint32_t sb = sa + A_STAGE;
    int row = tid >> 2;            // 0..127
    int seg = tid & 3;             // 16B segment in 64B row
    const int8_t* Asrc = g_Aq + (size_t)(m0 + row) * K_DIM + c * BK + seg * 16;
    const int8_t* Bsrc = g_Wq + (size_t)(n0 + row) * K_DIM + c * BK + seg * 16;
    cp_async16(sa + row * ROWB + seg * 16, Asrc);
    cp_async16(sb + row * ROWB + seg * 16, Bsrc);
    asm volatile("cp.async.commit_group;");
}

__global__ void __launch_bounds__(512, 1) gemm_kernel(const float* __restrict__ ws,
                                                      const float* __restrict__ bias,
                                                      float* __restrict__ out) {
    extern __shared__ __align__(1024) char smem[];
    const uint32_t sbase = smem_u32(smem);
    const int tid = threadIdx.x;
    const int wid = tid >> 5;
    const int lid = tid & 31;
    const int g   = lid >> 2;          // groupID 0..7
    const int t4  = lid & 3;           // threadID_in_group 0..3
    const int n0 = blockIdx.x * BN;
    const int m0 = blockIdx.y * BM;
    const int wm = wid >> 2;           // 0..3
    const int wn = wid & 3;            // 0..3
    const int mbase = wm * 32;
    const int nbase = wn * 32;

    float* xs_s = reinterpret_cast<float*>(smem + OFF_XS);
    float* ws_s = reinterpret_cast<float*>(smem + OFF_WS);

    // stage x-scales (padded stride 33 -> conflict-free column reads)
    for (int i = tid; i < BM * KB; i += 512) {
        int r = i >> 5, cb = i & 31;
        xs_s[r * XS_STRIDE + cb] = g_xs[(size_t)(m0 + r) * KB + cb];
    }
    if (tid < KB) ws_s[tid] = ws[(size_t)blockIdx.x * KB + tid];  // ws[n0/128][cb]

    // prologue: prefetch chunks 0..STAGES-2
    #pragma unroll
    for (int c = 0; c < STAGES - 1; c++) load_chunk(sbase, c, c, m0, n0, tid);
    __syncthreads();

    int32_t iacc[2][4][4] = {};
    float   facc[2][4][4] = {};

    for (int c = 0; c < NCHUNKS; c++) {
        const int stage = c & (STAGES - 1);
        if (c < NCHUNKS - 2)       asm volatile("cp.async.wait_group 2;");
        else if (c == NCHUNKS - 2) asm volatile("cp.async.wait_group 1;");
        else                       asm volatile("cp.async.wait_group 0;");
        __syncthreads();

        // prefetch chunk c+3 into the stage consumed in iter c-1
        if (c + STAGES - 1 < NCHUNKS)
            load_chunk(sbase, (c + STAGES - 1) & (STAGES - 1), c + STAGES - 1,
                       m0, n0, tid);

        const uint32_t sa = sbase + OFF_STG + stage * STAGE_BYTES;
        const uint32_t sb = sa + A_STAGE;

        #pragma unroll
        for (int ks = 0; ks < 2; ks++) {       // 2 x k32 steps per 64B chunk
            const int k0 = ks * 32;
            // A frags (PTX m16n8k32.s8): a0=(g,k0..15), a1=(g+8,k0..15),
            //                            a2=(g,k16..31), a3=(g+8,k16..31)
            uint32_t a[2][4];
            #pragma unroll
            for (int mi = 0; mi < 2; mi++) {
                uint32_t base = sa + (uint32_t)(mbase + mi * 16 + g) * ROWB + k0 + t4 * 4;
                a[mi][0] = lds32(base);
                a[mi][1] = lds32(base + 8 * ROWB);
                a[mi][2] = lds32(base + 16);
                a[mi][3] = lds32(base + 8 * ROWB + 16);
            }
            // B frags: b0=(k=4*t4.., n=g), b1=(+16)
            uint32_t bf[4][2];
            #pragma unroll
            for (int ni = 0; ni < 4; ni++) {
                uint32_t base = sb + (uint32_t)(nbase + ni * 8 + g) * ROWB + k0 + t4 * 4;
                bf[ni][0] = lds32(base);
                bf[ni][1] = lds32(base + 16);
            }
            #pragma unroll
            for (int mi = 0; mi < 2; mi++)
                #pragma unroll
                for (int ni = 0; ni < 4; ni++)
                    mma_s8(iacc[mi][ni], a[mi], bf[ni][0], bf[ni][1]);
        }

        // 128-K block boundary: rescale exact s32 partials into fp32
        if (c & 1) {
            const int cb = c >> 1;
            const float wsb = ws_s[cb];
            #pragma unroll
            for (int mi = 0; mi < 2; mi++) {
                int r0 = mbase + mi * 16 + g;
                float s0 = xs_s[r0 * XS_STRIDE + cb] * wsb;
                float s1 = xs_s[(r0 + 8) * XS_STRIDE + cb] * wsb;
                #pragma unroll
                for (int ni = 0; ni < 4; ni++) {
                    facc[mi][ni][0] += s0 * (float)iacc[mi][ni][0];
                    facc[mi][ni][1] += s0 * (float)iacc[mi][ni][1];
                    facc[mi][ni][2] += s1 * (float)iacc[mi][ni][2];
                    facc[mi][ni][3] += s1 * (float)iacc[mi][ni][3];
                    iacc[mi][ni][0] = 0; iacc[mi][ni][1] = 0;
                    iacc[mi][ni][2] = 0; iacc[mi][ni][3] = 0;
                }
            }
        }
    }

    // epilogue: bias add, direct stores (float2); C frag rows g/g+8, cols 2*t4
    #pragma unroll
    for (int mi = 0; mi < 2; mi++) {
        int r0 = m0 + mbase + mi * 16 + g;
        #pragma unroll
        for (int ni = 0; ni < 4; ni++) {
            int c0 = n0 + nbase + ni * 8 + t4 * 2;
            float b0 = __ldg(bias + c0), b1 = __ldg(bias + c0 + 1);
            float2 v0 = make_float2(facc[mi][ni][0] + b0, facc[mi][ni][1] + b1);
            float2 v1 = make_float2(facc[mi][ni][2] + b0, facc[mi][ni][3] + b1);
            *reinterpret_cast<float2*>(out + (size_t)r0 * N_DIM + c0) = v0;
            *reinterpret_cast<float2*>(out + (size_t)(r0 + 8) * N_DIM + c0) = v1;
        }
    }
}

// ---------------------------------------------------------------------------
// Launch
// ---------------------------------------------------------------------------
extern "C" void kernel_launch(void* const* d_in, const int* in_sizes, int n_in,
                              void* d_out, int out_size) {
    const float* x    = (const float*)d_in[0];
    const void*  wraw = d_in[1];                 // int8 OR promoted int32/float32
    const float* ws   = (const float*)d_in[2];
    const float* bias = (const float*)d_in[3];
    float* out = (float*)d_out;

    cudaFuncSetAttribute(gemm_kernel, cudaFuncAttributeMaxDynamicSharedMemorySize,
                         SMEM_BYTES);

    detect_w_kernel<<<1, 256>>>((const uint32_t*)wraw);
    convert_w_kernel<<<(size_t)N_DIM * K_DIM / 4 / 256, 256>>>(wraw);

    // 1 warp per (m, kb): 2048*32 warps, 8 warps per 256-thread block
    quant_x_kernel<<<(M_DIM * KB) / 8, 256>>>(x);

    dim3 grid(N_DIM / BN, M_DIM / BM);   // 32 x 16 = 512 CTAs
    gemm_kernel<<<grid, 512, SMEM_BYTES>>>(ws, bias, out);
}

// round 8
// speedup vs baseline: 1.3365x; 1.3365x over previous
#include <cuda_runtime.h>
#include <cstdint>
#include <cstddef>

// ---------------------------------------------------------------------------
// Problem dims (fixed)
// ---------------------------------------------------------------------------
static constexpr int M_DIM = 2048;
static constexpr int K_DIM = 4096;
static constexpr int N_DIM = 4096;
static constexpr int KB    = K_DIM / 128;     // 32 k-blocks of 128

// GEMM tiling
static constexpr int BM  = 128;
static constexpr int BN  = 128;
static constexpr int BKB = 128;               // bytes per chunk = one scale block
static constexpr int NCH = K_DIM / BKB;       // 32 chunks
static constexpr int STAGES = 3;
static constexpr int A_STAGE = BM * BKB;      // 16 KB
static constexpr int B_STAGE = BN * BKB;      // 16 KB
static constexpr int STAGE_BYTES = A_STAGE + B_STAGE;   // 32 KB

// SMEM layout
static constexpr int XS_STRIDE = 33;
static constexpr int OFF_XS  = 0;                       // 128*33*4 = 16896
static constexpr int OFF_WS  = 16896;                   // 32 floats
static constexpr int OFF_STG = 17408;                   // 1024-aligned
static constexpr int SMEM_BYTES = OFF_STG + STAGES * STAGE_BYTES;  // 115712

// Scratch (allocation-free rule: __device__ globals)
__device__ __align__(1024) int8_t g_Aq[(size_t)M_DIM * K_DIM];  // 8 MB
__device__ __align__(1024) int8_t g_Wq[(size_t)N_DIM * K_DIM];  // 16 MB
__device__ __align__(256)  float  g_xs[(size_t)M_DIM * KB];     // 256 KB
__device__ int g_wfmt;   // 0=int8, 1=int32, 2=float32

// ---------------------------------------------------------------------------
// Helpers
// ---------------------------------------------------------------------------
__device__ __forceinline__ uint32_t smem_u32(const void* p) {
    uint32_t a;
    asm("{ .reg .u64 t; cvta.to.shared.u64 t, %1; cvt.u32.u64 %0, t; }"
        : "=r"(a) : "l"(p));
    return a;
}

#define SWZ128(off) ((off) ^ (((off) >> 3) & 0x70))

__device__ __forceinline__ void cp_async16(uint32_t dst, const void* src) {
    asm volatile("cp.async.cg.shared.global [%0], [%1], 16;" :: "r"(dst), "l"(src));
}

__device__ __forceinline__ void ldsm4(uint32_t& r0, uint32_t& r1, uint32_t& r2,
                                      uint32_t& r3, uint32_t addr) {
    asm volatile("ldmatrix.sync.aligned.m8n8.x4.shared.b16 {%0,%1,%2,%3}, [%4];"
                 : "=r"(r0), "=r"(r1), "=r"(r2), "=r"(r3) : "r"(addr));
}

__device__ __forceinline__ void mma_s8(int32_t* c, const uint32_t* a,
                                       uint32_t b0, uint32_t b1) {
    asm volatile(
        "mma.sync.aligned.m16n8k32.row.col.s32.s8.s8.s32 "
        "{%0,%1,%2,%3}, {%4,%5,%6,%7}, {%8,%9}, {%0,%1,%2,%3};"
        : "+r"(c[0]), "+r"(c[1]), "+r"(c[2]), "+r"(c[3])
        : "r"(a[0]), "r"(a[1]), "r"(a[2]), "r"(a[3]), "r"(b0), "r"(b1));
}

// first k-step of each chunk: D = A*B + 0  (kills the accumulator-zeroing MOVs)
__device__ __forceinline__ void mma_s8_zc(int32_t* d, const uint32_t* a,
                                          uint32_t b0, uint32_t b1) {
    asm volatile(
        "mma.sync.aligned.m16n8k32.row.col.s32.s8.s8.s32 "
        "{%0,%1,%2,%3}, {%4,%5,%6,%7}, {%8,%9}, {%10,%10,%10,%10};"
        : "=r"(d[0]), "=r"(d[1]), "=r"(d[2]), "=r"(d[3])
        : "r"(a[0]), "r"(a[1]), "r"(a[2]), "r"(a[3]), "r"(b0), "r"(b1), "r"(0u));
}

// ---------------------------------------------------------------------------
// Kernel 0a: detect storage format of w_q (harness promotes int8 -> 4B dtype)
// ---------------------------------------------------------------------------
__global__ void detect_w_kernel(const uint32_t* __restrict__ w) {
    __shared__ int s_int, s_flt;
    if (threadIdx.x == 0) { s_int = 1; s_flt = 1; }
    __syncthreads();
    int ok_int = 1, ok_flt = 1;
    for (int i = threadIdx.x; i < 4096; i += 256) {
        uint32_t u = w[i];
        int v = (int)u;
        if (v < -127 || v > 127) ok_int = 0;
        float f = __uint_as_float(u);
        if (!(fabsf(f) <= 127.0f && rintf(f) == f)) ok_flt = 0;
    }
    if (!ok_int) atomicAnd(&s_int, 0);
    if (!ok_flt) atomicAnd(&s_flt, 0);
    __syncthreads();
    if (threadIdx.x == 0) g_wfmt = s_int ? 1 : (s_flt ? 2 : 0);
}

// ---------------------------------------------------------------------------
// Kernel 0b: canonicalize w_q -> int8 g_Wq
// ---------------------------------------------------------------------------
__global__ void __launch_bounds__(256) convert_w_kernel(const void* __restrict__ wsrc) {
    const int fmt = g_wfmt;
    size_t t = (size_t)blockIdx.x * 256 + threadIdx.x;   // 0 .. N*K/4-1
    char4 q;
    if (fmt == 1) {
        int4 v = reinterpret_cast<const int4*>(wsrc)[t];
        q = make_char4((char)v.x, (char)v.y, (char)v.z, (char)v.w);
    } else if (fmt == 2) {
        float4 v = reinterpret_cast<const float4*>(wsrc)[t];
        q = make_char4((char)(int)v.x, (char)(int)v.y,
                       (char)(int)v.z, (char)(int)v.w);
    } else {
        q = reinterpret_cast<const char4*>(wsrc)[t];
    }
    reinterpret_cast<char4*>(g_Wq)[t] = q;
}

// ---------------------------------------------------------------------------
// Kernel 1: per-(row, 128-block) int8 quantization of x (matches jnp exactly)
// ---------------------------------------------------------------------------
__global__ void __launch_bounds__(256) quant_x_kernel(const float* __restrict__ x) {
    int warp = (blockIdx.x * blockDim.x + threadIdx.x) >> 5;
    int lane = threadIdx.x & 31;
    int m  = warp >> 5;
    int kb = warp & 31;

    const float4* xp = reinterpret_cast<const float4*>(x + (size_t)m * K_DIM + kb * 128);
    float4 v = xp[lane];
    float a = fmaxf(fmaxf(fabsf(v.x), fabsf(v.y)), fmaxf(fabsf(v.z), fabsf(v.w)));
    #pragma unroll
    for (int o = 16; o; o >>= 1) a = fmaxf(a, __shfl_xor_sync(0xffffffffu, a, o));
    float s = fmaxf(a, 1e-8f) * (1.0f / 127.0f);

    char4 q;
    q.x = (char)(int)fminf(fmaxf(rintf(__fdiv_rn(v.x, s)), -127.f), 127.f);
    q.y = (char)(int)fminf(fmaxf(rintf(__fdiv_rn(v.y, s)), -127.f), 127.f);
    q.z = (char)(int)fminf(fmaxf(rintf(__fdiv_rn(v.z, s)), -127.f), 127.f);
    q.w = (char)(int)fminf(fmaxf(rintf(__fdiv_rn(v.w, s)), -127.f), 127.f);
    reinterpret_cast<char4*>(g_Aq + (size_t)m * K_DIM + kb * 128)[lane] = q;
    if (lane == 0) g_xs[(size_t)m * KB + kb] = s;
}

// ---------------------------------------------------------------------------
// Kernel 2: int8 GEMM, v2.
// CTA 128x128, 512 thr (16 warps 4x4, warp tile 32x32), 3-stage cp.async,
// 128B k-chunks (= one scale block), SW128 swizzle + ldmatrix.x4 operands,
// per-chunk exact-s32 -> fp32 rescale.
// ---------------------------------------------------------------------------
__device__ __forceinline__ void load_chunk(uint32_t sbase, int stage, int c,
                                           int m0, int n0, int tid) {
    uint32_t sa = sbase + OFF_STG + stage * STAGE_BYTES;
    uint32_t sb = sa + A_STAGE;
    const int8_t* Ab = g_Aq + (size_t)m0 * K_DIM + c * BKB;
    const int8_t* Bb = g_Wq + (size_t)n0 * K_DIM + c * BKB;
    #pragma unroll
    for (int i = 0; i < 2; i++) {          // A: 128 rows * 8 segs = 1024 ops
        int s = tid + i * 512;
        int row = s >> 3, seg = s & 7;
        cp_async16(sa + SWZ128(row * BKB + seg * 16),
                   Ab + (size_t)row * K_DIM + seg * 16);
    }
    #pragma unroll
    for (int i = 0; i < 2; i++) {          // B: 128 rows * 8 segs
        int s = tid + i * 512;
        int row = s >> 3, seg = s & 7;
        cp_async16(sb + SWZ128(row * BKB + seg * 16),
                   Bb + (size_t)row * K_DIM + seg * 16);
    }
    asm volatile("cp.async.commit_group;");
}

__global__ void __launch_bounds__(512, 1) gemm_kernel(const float* __restrict__ ws,
                                                      const float* __restrict__ bias,
                                                      float* __restrict__ out) {
    extern __shared__ __align__(1024) char smem[];
    const uint32_t sbase = smem_u32(smem);
    const int tid = threadIdx.x;
    const int wid = tid >> 5;
    const int lid = tid & 31;
    const int g   = lid >> 2;          // groupID 0..7
    const int t4  = lid & 3;
    const int n0 = blockIdx.x * BN;
    const int m0 = blockIdx.y * BM;
    const int mbase = (wid >> 2) * 32;
    const int nbase = (wid & 3) * 32;

    float* xs_s = reinterpret_cast<float*>(smem + OFF_XS);
    float* ws_s = reinterpret_cast<float*>(smem + OFF_WS);

    // ldmatrix lane addressing (within a 16-row x 32-byte k-step window):
    //   matrices: (rows 0-7,k0-15)(rows 8-15,k0-15)(rows 0-7,k16-31)(rows 8-15,k16-31)
    const int lrow = (lid & 7) + ((lid >> 3) & 1) * 8;   // row within 16
    const int lcol = (lid >> 4) * 16;                    // 0 or 16

    for (int i = tid; i < BM * KB; i += 512) {
        int r = i >> 5, cb = i & 31;
        xs_s[r * XS_STRIDE + cb] = g_xs[(size_t)(m0 + r) * KB + cb];
    }
    if (tid < KB) ws_s[tid] = ws[(size_t)blockIdx.x * KB + tid];

    // prologue: prefetch chunks 0,1
    load_chunk(sbase, 0, 0, m0, n0, tid);
    load_chunk(sbase, 1, 1, m0, n0, tid);
    __syncthreads();   // xs/ws visible before first use

    float facc[2][4][4] = {};

    int stage = 0;
    for (int c = 0; c < NCH; c++) {
        if (c < NCH - 1) asm volatile("cp.async.wait_group 1;");
        else             asm volatile("cp.async.wait_group 0;");
        __syncthreads();

        if (c + 2 < NCH) {
            int ls = stage + 2; if (ls >= STAGES) ls -= STAGES;
            load_chunk(sbase, ls, c + 2, m0, n0, tid);
        }

        const uint32_t sa = sbase + OFF_STG + stage * STAGE_BYTES;
        const uint32_t sb = sa + A_STAGE;

        int32_t iacc[2][4][4];
        #pragma unroll
        for (int ks = 0; ks < 4; ks++) {          // 4 x k32 per 128B chunk
            const int k0 = ks * 32;
            uint32_t a[2][4], bb[2][4];
            #pragma unroll
            for (int mi = 0; mi < 2; mi++) {
                int r = mbase + mi * 16 + lrow;
                ldsm4(a[mi][0], a[mi][1], a[mi][2], a[mi][3],
                      sa + SWZ128((uint32_t)(r * BKB) + k0 + lcol));
            }
            #pragma unroll
            for (int nj = 0; nj < 2; nj++) {
                int r = nbase + nj * 16 + lrow;
                ldsm4(bb[nj][0], bb[nj][1], bb[nj][2], bb[nj][3],
                      sb + SWZ128((uint32_t)(r * BKB) + k0 + lcol));
            }
            #pragma unroll
            for (int mi = 0; mi < 2; mi++)
                #pragma unroll
                for (int ni = 0; ni < 4; ni++) {
                    int nj = ni >> 1, w = ni & 1;
                    if (ks == 0)
                        mma_s8_zc(iacc[mi][ni], a[mi], bb[nj][w], bb[nj][w + 2]);
                    else
                        mma_s8(iacc[mi][ni], a[mi], bb[nj][w], bb[nj][w + 2]);
                }
        }

        // chunk == one 128-K scale block: rescale exact s32 into fp32
        const float wsb = ws_s[c];
        #pragma unroll
        for (int mi = 0; mi < 2; mi++) {
            int r0 = mbase + mi * 16 + g;
            float s0 = xs_s[r0 * XS_STRIDE + c] * wsb;
            float s1 = xs_s[(r0 + 8) * XS_STRIDE + c] * wsb;
            #pragma unroll
            for (int ni = 0; ni < 4; ni++) {
                facc[mi][ni][0] += s0 * (float)iacc[mi][ni][0];
                facc[mi][ni][1] += s0 * (float)iacc[mi][ni][1];
                facc[mi][ni][2] += s1 * (float)iacc[mi][ni][2];
                facc[mi][ni][3] += s1 * (float)iacc[mi][ni][3];
            }
        }

        stage++; if (stage >= STAGES) stage = 0;
    }

    // epilogue: bias add, direct float2 stores; C frag rows g/g+8, cols 2*t4
    #pragma unroll
    for (int mi = 0; mi < 2; mi++) {
        int r0 = m0 + mbase + mi * 16 + g;
        #pragma unroll
        for (int ni = 0; ni < 4; ni++) {
            int c0 = n0 + nbase + ni * 8 + t4 * 2;
            float b0 = __ldg(bias + c0), b1 = __ldg(bias + c0 + 1);
            float2 v0 = make_float2(facc[mi][ni][0] + b0, facc[mi][ni][1] + b1);
            float2 v1 = make_float2(facc[mi][ni][2] + b0, facc[mi][ni][3] + b1);
            *reinterpret_cast<float2*>(out + (size_t)r0 * N_DIM + c0) = v0;
            *reinterpret_cast<float2*>(out + (size_t)(r0 + 8) * N_DIM + c0) = v1;
        }
    }
}

// ---------------------------------------------------------------------------
// Launch
// ---------------------------------------------------------------------------
extern "C" void kernel_launch(void* const* d_in, const int* in_sizes, int n_in,
                              void* d_out, int out_size) {
    const float* x    = (const float*)d_in[0];
    const void*  wraw = d_in[1];                 // int8 OR promoted int32/float32
    const float* ws   = (const float*)d_in[2];
    const float* bias = (const float*)d_in[3];
    float* out = (float*)d_out;

    cudaFuncSetAttribute(gemm_kernel, cudaFuncAttributeMaxDynamicSharedMemorySize,
                         SMEM_BYTES);

    detect_w_kernel<<<1, 256>>>((const uint32_t*)wraw);
    convert_w_kernel<<<(size_t)N_DIM * K_DIM / 4 / 256, 256>>>(wraw);
    quant_x_kernel<<<(M_DIM * KB) / 8, 256>>>(x);

    dim3 grid(N_DIM / BN, M_DIM / BM);   // 32 x 16 = 512 CTAs
    gemm_kernel<<<grid, 512, SMEM_BYTES>>>(ws, bias, out);
}

// round 9
// speedup vs baseline: 1.5798x; 1.1820x over previous
#include <cuda_runtime.h>
#include <cstdint>
#include <cstddef>

// ---------------------------------------------------------------------------
// Problem dims (fixed)
// ---------------------------------------------------------------------------
static constexpr int M_DIM = 2048;
static constexpr int K_DIM = 4096;
static constexpr int N_DIM = 4096;
static constexpr int KB    = K_DIM / 128;     // 32 k-blocks of 128

// GEMM tiling: 64x128 CTA, 256 thr (8 warps 2x4, warp tile 32x32), 2 CTAs/SM
static constexpr int BM  = 64;
static constexpr int BN  = 128;
static constexpr int BKB = 128;               // bytes per chunk = one scale block
static constexpr int NCH = K_DIM / BKB;       // 32 chunks
static constexpr int STAGES = 3;
static constexpr int A_STAGE = BM * BKB;      // 8 KB
static constexpr int B_STAGE = BN * BKB;      // 16 KB
static constexpr int STAGE_BYTES = A_STAGE + B_STAGE;   // 24 KB

// SMEM layout
static constexpr int XS_STRIDE = 33;
static constexpr int OFF_XS  = 0;                       // 64*33*4 = 8448
static constexpr int OFF_WS  = 8448;                    // 32 floats
static constexpr int OFF_STG = 9216;                    // 1024-aligned
static constexpr int SMEM_BYTES = OFF_STG + STAGES * STAGE_BYTES;  // 82944

// Scratch (allocation-free rule: __device__ globals)
__device__ __align__(1024) int8_t g_Aq[(size_t)M_DIM * K_DIM];  // 8 MB
__device__ __align__(1024) int8_t g_Wq[(size_t)N_DIM * K_DIM];  // 16 MB
__device__ __align__(256)  float  g_xs[(size_t)M_DIM * KB];     // 256 KB
__device__ int g_wfmt;   // 0=int8, 1=int32, 2=float32

// ---------------------------------------------------------------------------
// Helpers
// ---------------------------------------------------------------------------
__device__ __forceinline__ uint32_t smem_u32(const void* p) {
    uint32_t a;
    asm("{ .reg .u64 t; cvta.to.shared.u64 t, %1; cvt.u32.u64 %0, t; }"
        : "=r"(a) : "l"(p));
    return a;
}

#define SWZ128(off) ((off) ^ (((off) >> 3) & 0x70))

__device__ __forceinline__ void cp_async16(uint32_t dst, const void* src) {
    asm volatile("cp.async.cg.shared.global [%0], [%1], 16;" :: "r"(dst), "l"(src));
}

__device__ __forceinline__ void ldsm4(uint32_t& r0, uint32_t& r1, uint32_t& r2,
                                      uint32_t& r3, uint32_t addr) {
    asm volatile("ldmatrix.sync.aligned.m8n8.x4.shared.b16 {%0,%1,%2,%3}, [%4];"
                 : "=r"(r0), "=r"(r1), "=r"(r2), "=r"(r3) : "r"(addr));
}

__device__ __forceinline__ void mma_s8(int32_t* c, const uint32_t* a,
                                       uint32_t b0, uint32_t b1) {
    asm volatile(
        "mma.sync.aligned.m16n8k32.row.col.s32.s8.s8.s32 "
        "{%0,%1,%2,%3}, {%4,%5,%6,%7}, {%8,%9}, {%0,%1,%2,%3};"
        : "+r"(c[0]), "+r"(c[1]), "+r"(c[2]), "+r"(c[3])
        : "r"(a[0]), "r"(a[1]), "r"(a[2]), "r"(a[3]), "r"(b0), "r"(b1));
}

__device__ __forceinline__ void mma_s8_zc(int32_t* d, const uint32_t* a,
                                          uint32_t b0, uint32_t b1) {
    asm volatile(
        "mma.sync.aligned.m16n8k32.row.col.s32.s8.s8.s32 "
        "{%0,%1,%2,%3}, {%4,%5,%6,%7}, {%8,%9}, {%10,%10,%10,%10};"
        : "=r"(d[0]), "=r"(d[1]), "=r"(d[2]), "=r"(d[3])
        : "r"(a[0]), "r"(a[1]), "r"(a[2]), "r"(a[3]), "r"(b0), "r"(b1), "r"(0u));
}

// ---------------------------------------------------------------------------
// Kernel 0a: detect storage format of w_q (harness promotes int8 -> 4B dtype)
// ---------------------------------------------------------------------------
__global__ void detect_w_kernel(const uint32_t* __restrict__ w) {
    __shared__ int s_int, s_flt;
    if (threadIdx.x == 0) { s_int = 1; s_flt = 1; }
    __syncthreads();
    int ok_int = 1, ok_flt = 1;
    for (int i = threadIdx.x; i < 4096; i += 256) {
        uint32_t u = w[i];
        int v = (int)u;
        if (v < -127 || v > 127) ok_int = 0;
        float f = __uint_as_float(u);
        if (!(fabsf(f) <= 127.0f && rintf(f) == f)) ok_flt = 0;
    }
    if (!ok_int) atomicAnd(&s_int, 0);
    if (!ok_flt) atomicAnd(&s_flt, 0);
    __syncthreads();
    if (threadIdx.x == 0) g_wfmt = s_int ? 1 : (s_flt ? 2 : 0);
}

// ---------------------------------------------------------------------------
// Kernel 0b: canonicalize w_q -> int8 g_Wq
// ---------------------------------------------------------------------------
__global__ void __launch_bounds__(256) convert_w_kernel(const void* __restrict__ wsrc) {
    const int fmt = g_wfmt;
    size_t t = (size_t)blockIdx.x * 256 + threadIdx.x;   // 0 .. N*K/4-1
    char4 q;
    if (fmt == 1) {
        int4 v = reinterpret_cast<const int4*>(wsrc)[t];
        q = make_char4((char)v.x, (char)v.y, (char)v.z, (char)v.w);
    } else if (fmt == 2) {
        float4 v = reinterpret_cast<const float4*>(wsrc)[t];
        q = make_char4((char)(int)v.x, (char)(int)v.y,
                       (char)(int)v.z, (char)(int)v.w);
    } else {
        q = reinterpret_cast<const char4*>(wsrc)[t];
    }
    reinterpret_cast<char4*>(g_Wq)[t] = q;
}

// ---------------------------------------------------------------------------
// Kernel 1: per-(row, 128-block) int8 quantization of x (matches jnp exactly)
// ---------------------------------------------------------------------------
__global__ void __launch_bounds__(256) quant_x_kernel(const float* __restrict__ x) {
    int warp = (blockIdx.x * blockDim.x + threadIdx.x) >> 5;
    int lane = threadIdx.x & 31;
    int m  = warp >> 5;
    int kb = warp & 31;

    const float4* xp = reinterpret_cast<const float4*>(x + (size_t)m * K_DIM + kb * 128);
    float4 v = xp[lane];
    float a = fmaxf(fmaxf(fabsf(v.x), fabsf(v.y)), fmaxf(fabsf(v.z), fabsf(v.w)));
    #pragma unroll
    for (int o = 16; o; o >>= 1) a = fmaxf(a, __shfl_xor_sync(0xffffffffu, a, o));
    float s = fmaxf(a, 1e-8f) * (1.0f / 127.0f);

    char4 q;
    q.x = (char)(int)fminf(fmaxf(rintf(__fdiv_rn(v.x, s)), -127.f), 127.f);
    q.y = (char)(int)fminf(fmaxf(rintf(__fdiv_rn(v.y, s)), -127.f), 127.f);
    q.z = (char)(int)fminf(fmaxf(rintf(__fdiv_rn(v.z, s)), -127.f), 127.f);
    q.w = (char)(int)fminf(fmaxf(rintf(__fdiv_rn(v.w, s)), -127.f), 127.f);
    reinterpret_cast<char4*>(g_Aq + (size_t)m * K_DIM + kb * 128)[lane] = q;
    if (lane == 0) g_xs[(size_t)m * KB + kb] = s;
}

// ---------------------------------------------------------------------------
// Kernel 2: int8 GEMM, v3. CTA 64x128, 256 thr, 2 CTAs/SM for barrier overlap.
// 3-stage cp.async, 128B chunks (= scale block), SW128 + ldmatrix.x4.
// ---------------------------------------------------------------------------
__device__ __forceinline__ void load_chunk(uint32_t sbase, int stage, int c,
                                           int m0, int n0, int tid) {
    uint32_t sa = sbase + OFF_STG + stage * STAGE_BYTES;
    uint32_t sb = sa + A_STAGE;
    const int8_t* Ab = g_Aq + (size_t)m0 * K_DIM + c * BKB;
    const int8_t* Bb = g_Wq + (size_t)n0 * K_DIM + c * BKB;
    {   // A: 64 rows * 8 segs = 512 ops -> 2 per thread
        #pragma unroll
        for (int i = 0; i < 2; i++) {
            int s = tid + i * 256;
            int row = s >> 3, seg = s & 7;
            cp_async16(sa + SWZ128(row * BKB + seg * 16),
                       Ab + (size_t)row * K_DIM + seg * 16);
        }
    }
    {   // B: 128 rows * 8 segs = 1024 ops -> 4 per thread
        #pragma unroll
        for (int i = 0; i < 4; i++) {
            int s = tid + i * 256;
            int row = s >> 3, seg = s & 7;
            cp_async16(sb + SWZ128(row * BKB + seg * 16),
                       Bb + (size_t)row * K_DIM + seg * 16);
        }
    }
    asm volatile("cp.async.commit_group;");
}

__global__ void __launch_bounds__(256, 2) gemm_kernel(const float* __restrict__ ws,
                                                      const float* __restrict__ bias,
                                                      float* __restrict__ out) {
    extern __shared__ __align__(1024) char smem[];
    const uint32_t sbase = smem_u32(smem);
    const int tid = threadIdx.x;
    const int wid = tid >> 5;
    const int lid = tid & 31;
    const int g   = lid >> 2;          // groupID 0..7
    const int t4  = lid & 3;
    const int n0 = blockIdx.x * BN;
    const int m0 = blockIdx.y * BM;
    const int mbase = (wid >> 2) * 32;     // 2 m-warps
    const int nbase = (wid & 3) * 32;      // 4 n-warps

    float* xs_s = reinterpret_cast<float*>(smem + OFF_XS);
    float* ws_s = reinterpret_cast<float*>(smem + OFF_WS);

    // ldmatrix lane addressing within 16-row x 32B window
    const int lrow = (lid & 7) + ((lid >> 3) & 1) * 8;
    const int lcol = (lid >> 4) * 16;

    for (int i = tid; i < BM * KB; i += 256) {
        int r = i >> 5, cb = i & 31;
        xs_s[r * XS_STRIDE + cb] = g_xs[(size_t)(m0 + r) * KB + cb];
    }
    if (tid < KB) ws_s[tid] = ws[(size_t)blockIdx.x * KB + tid];

    load_chunk(sbase, 0, 0, m0, n0, tid);
    load_chunk(sbase, 1, 1, m0, n0, tid);
    __syncthreads();

    float facc[2][4][4] = {};

    int stage = 0;
    for (int c = 0; c < NCH; c++) {
        if (c < NCH - 1) asm volatile("cp.async.wait_group 1;");
        else             asm volatile("cp.async.wait_group 0;");
        __syncthreads();

        if (c + 2 < NCH) {
            int ls = stage + 2; if (ls >= STAGES) ls -= STAGES;
            load_chunk(sbase, ls, c + 2, m0, n0, tid);
        }

        const uint32_t sa = sbase + OFF_STG + stage * STAGE_BYTES;
        const uint32_t sb = sa + A_STAGE;

        int32_t iacc[2][4][4];
        #pragma unroll
        for (int ks = 0; ks < 4; ks++) {
            const int k0 = ks * 32;
            uint32_t a[2][4], bb[2][4];
            #pragma unroll
            for (int mi = 0; mi < 2; mi++) {
                int r = mbase + mi * 16 + lrow;
                ldsm4(a[mi][0], a[mi][1], a[mi][2], a[mi][3],
                      sa + SWZ128((uint32_t)(r * BKB) + k0 + lcol));
            }
            #pragma unroll
            for (int nj = 0; nj < 2; nj++) {
                int r = nbase + nj * 16 + lrow;
                ldsm4(bb[nj][0], bb[nj][1], bb[nj][2], bb[nj][3],
                      sb + SWZ128((uint32_t)(r * BKB) + k0 + lcol));
            }
            #pragma unroll
            for (int mi = 0; mi < 2; mi++)
                #pragma unroll
                for (int ni = 0; ni < 4; ni++) {
                    int nj = ni >> 1, w = ni & 1;
                    if (ks == 0)
                        mma_s8_zc(iacc[mi][ni], a[mi], bb[nj][w], bb[nj][w + 2]);
                    else
                        mma_s8(iacc[mi][ni], a[mi], bb[nj][w], bb[nj][w + 2]);
                }
        }

        const float wsb = ws_s[c];
        #pragma unroll
        for (int mi = 0; mi < 2; mi++) {
            int r0 = mbase + mi * 16 + g;
            float s0 = xs_s[r0 * XS_STRIDE + c] * wsb;
            float s1 = xs_s[(r0 + 8) * XS_STRIDE + c] * wsb;
            #pragma unroll
            for (int ni = 0; ni < 4; ni++) {
                facc[mi][ni][0] += s0 * (float)iacc[mi][ni][0];
                facc[mi][ni][1] += s0 * (float)iacc[mi][ni][1];
                facc[mi][ni][2] += s1 * (float)iacc[mi][ni][2];
                facc[mi][ni][3] += s1 * (float)iacc[mi][ni][3];
            }
        }

        stage++; if (stage >= STAGES) stage = 0;
    }

    // epilogue: bias add, direct float2 stores; C frag rows g/g+8, cols 2*t4
    #pragma unroll
    for (int mi = 0; mi < 2; mi++) {
        int r0 = m0 + mbase + mi * 16 + g;
        #pragma unroll
        for (int ni = 0; ni < 4; ni++) {
            int c0 = n0 + nbase + ni * 8 + t4 * 2;
            float b0 = __ldg(bias + c0), b1 = __ldg(bias + c0 + 1);
            float2 v0 = make_float2(facc[mi][ni][0] + b0, facc[mi][ni][1] + b1);
            float2 v1 = make_float2(facc[mi][ni][2] + b0, facc[mi][ni][3] + b1);
            *reinterpret_cast<float2*>(out + (size_t)r0 * N_DIM + c0) = v0;
            *reinterpret_cast<float2*>(out + (size_t)(r0 + 8) * N_DIM + c0) = v1;
        }
    }
}

// ---------------------------------------------------------------------------
// Launch
// ---------------------------------------------------------------------------
extern "C" void kernel_launch(void* const* d_in, const int* in_sizes, int n_in,
                              void* d_out, int out_size) {
    const float* x    = (const float*)d_in[0];
    const void*  wraw = d_in[1];                 // int8 OR promoted int32/float32
    const float* ws   = (const float*)d_in[2];
    const float* bias = (const float*)d_in[3];
    float* out = (float*)d_out;

    cudaFuncSetAttribute(gemm_kernel, cudaFuncAttributeMaxDynamicSharedMemorySize,
                         SMEM_BYTES);

    detect_w_kernel<<<1, 256>>>((const uint32_t*)wraw);
    convert_w_kernel<<<(size_t)N_DIM * K_DIM / 4 / 256, 256>>>(wraw);
    quant_x_kernel<<<(M_DIM * KB) / 8, 256>>>(x);

    dim3 grid(N_DIM / BN, M_DIM / BM);   // 32 x 32 = 1024 CTAs
    gemm_kernel<<<grid, 256, SMEM_BYTES>>>(ws, bias, out);
}

// round 10
// speedup vs baseline: 1.6378x; 1.0367x over previous
#include <cuda_runtime.h>
#include <cstdint>
#include <cstddef>

// ---------------------------------------------------------------------------
// Problem dims (fixed)
// ---------------------------------------------------------------------------
static constexpr int M_DIM = 2048;
static constexpr int K_DIM = 4096;
static constexpr int N_DIM = 4096;
static constexpr int KB    = K_DIM / 128;     // 32 k-blocks of 128

// GEMM tiling: 64x128 CTA, 256 thr (8 warps 2x4, warp tile 32x32), 2 CTAs/SM
static constexpr int BM  = 64;
static constexpr int BN  = 128;
static constexpr int BKB = 128;               // bytes per chunk = one scale block
static constexpr int NCH = K_DIM / BKB;       // 32 chunks
static constexpr int STAGES = 4;
static constexpr int A_STAGE = BM * BKB;      // 8 KB
static constexpr int B_STAGE = BN * BKB;      // 16 KB
static constexpr int STAGE_BYTES = A_STAGE + B_STAGE;   // 24 KB

// SMEM layout
static constexpr int XS_STRIDE = 33;
static constexpr int OFF_XS  = 0;                       // 64*33*4 = 8448
static constexpr int OFF_WS  = 8448;                    // 32 floats
static constexpr int OFF_STG = 9216;                    // 1024-aligned
static constexpr int SMEM_BYTES = OFF_STG + STAGES * STAGE_BYTES;  // 107520

// Prep kernel split
static constexpr int WBLK = (N_DIM * K_DIM) / 1024;     // 16384 w-convert blocks
static constexpr int XBLK = (M_DIM * KB) / 8;           // 8192 x-quant blocks

// Scratch (allocation-free rule: __device__ globals)
__device__ __align__(1024) int8_t g_Aq[(size_t)M_DIM * K_DIM];  // 8 MB
__device__ __align__(1024) int8_t g_Wq[(size_t)N_DIM * K_DIM];  // 16 MB
__device__ __align__(256)  float  g_xs[(size_t)M_DIM * KB];     // 256 KB

// ---------------------------------------------------------------------------
// Helpers
// ---------------------------------------------------------------------------
__device__ __forceinline__ uint32_t smem_u32(const void* p) {
    uint32_t a;
    asm("{ .reg .u64 t; cvta.to.shared.u64 t, %1; cvt.u32.u64 %0, t; }"
        : "=r"(a) : "l"(p));
    return a;
}

#define SWZ128(off) ((off) ^ (((off) >> 3) & 0x70))

__device__ __forceinline__ void cp_async16(uint32_t dst, const void* src) {
    asm volatile("cp.async.cg.shared.global [%0], [%1], 16;" :: "r"(dst), "l"(src));
}

__device__ __forceinline__ void ldsm4(uint32_t& r0, uint32_t& r1, uint32_t& r2,
                                      uint32_t& r3, uint32_t addr) {
    asm volatile("ldmatrix.sync.aligned.m8n8.x4.shared.b16 {%0,%1,%2,%3}, [%4];"
                 : "=r"(r0), "=r"(r1), "=r"(r2), "=r"(r3) : "r"(addr));
}

__device__ __forceinline__ void mma_s8(int32_t* c, const uint32_t* a,
                                       uint32_t b0, uint32_t b1) {
    asm volatile(
        "mma.sync.aligned.m16n8k32.row.col.s32.s8.s8.s32 "
        "{%0,%1,%2,%3}, {%4,%5,%6,%7}, {%8,%9}, {%0,%1,%2,%3};"
        : "+r"(c[0]), "+r"(c[1]), "+r"(c[2]), "+r"(c[3])
        : "r"(a[0]), "r"(a[1]), "r"(a[2]), "r"(a[3]), "r"(b0), "r"(b1));
}

__device__ __forceinline__ void mma_s8_zc(int32_t* d, const uint32_t* a,
                                          uint32_t b0, uint32_t b1) {
    asm volatile(
        "mma.sync.aligned.m16n8k32.row.col.s32.s8.s8.s32 "
        "{%0,%1,%2,%3}, {%4,%5,%6,%7}, {%8,%9}, {%10,%10,%10,%10};"
        : "=r"(d[0]), "=r"(d[1]), "=r"(d[2]), "=r"(d[3])
        : "r"(a[0]), "r"(a[1]), "r"(a[2]), "r"(a[3]), "r"(b0), "r"(b1), "r"(0u));
}

// ---------------------------------------------------------------------------
// Kernel 1: fused prep.
// Blocks [0, WBLK):       convert w_q -> int8 g_Wq, with inline format detect
//                         (fixed 64-word window; deterministic, L2-resident).
// Blocks [WBLK, +XBLK):   per-(row, 128-block) int8 quantization of x.
// ---------------------------------------------------------------------------
__global__ void __launch_bounds__(256) prep_kernel(const uint32_t* __restrict__ wraw,
                                                   const float* __restrict__ x) {
    const int b = blockIdx.x;
    if (b < WBLK) {
        // --- inline format detect over words [0, 64) ---
        __shared__ int s_flags;            // bit0: int32 ok, bit1: float32 ok
        if (threadIdx.x == 0) s_flags = 3;
        __syncthreads();
        if (threadIdx.x < 64) {
            uint32_t u = wraw[threadIdx.x];
            int v = (int)u;
            float f = __uint_as_float(u);
            int clr = ((v < -127 || v > 127) ? 1 : 0)
                    | (!(fabsf(f) <= 127.0f && rintf(f) == f) ? 2 : 0);
            if (clr) atomicAnd(&s_flags, ~clr);
        }
        __syncthreads();
        const int fmt = (s_flags & 1) ? 1 : ((s_flags & 2) ? 2 : 0);

        // --- convert 4 elems/thread ---
        size_t t = (size_t)b * 256 + threadIdx.x;
        char4 q;
        if (fmt == 1) {
            int4 v = reinterpret_cast<const int4*>(wraw)[t];
            q = make_char4((char)v.x, (char)v.y, (char)v.z, (char)v.w);
        } else if (fmt == 2) {
            float4 v = reinterpret_cast<const float4*>(wraw)[t];
            q = make_char4((char)(int)v.x, (char)(int)v.y,
                           (char)(int)v.z, (char)(int)v.w);
        } else {
            q = reinterpret_cast<const char4*>(wraw)[t];
        }
        reinterpret_cast<char4*>(g_Wq)[t] = q;
    } else {
        // --- x quantization: one warp per (m, kb), matches jnp exactly ---
        int warp = ((b - WBLK) * 256 + threadIdx.x) >> 5;
        int lane = threadIdx.x & 31;
        int m  = warp >> 5;
        int kb = warp & 31;

        const float4* xp =
            reinterpret_cast<const float4*>(x + (size_t)m * K_DIM + kb * 128);
        float4 v = xp[lane];
        float a = fmaxf(fmaxf(fabsf(v.x), fabsf(v.y)), fmaxf(fabsf(v.z), fabsf(v.w)));
        #pragma unroll
        for (int o = 16; o; o >>= 1) a = fmaxf(a, __shfl_xor_sync(0xffffffffu, a, o));
        float s = fmaxf(a, 1e-8f) * (1.0f / 127.0f);

        char4 q;
        q.x = (char)(int)fminf(fmaxf(rintf(__fdiv_rn(v.x, s)), -127.f), 127.f);
        q.y = (char)(int)fminf(fmaxf(rintf(__fdiv_rn(v.y, s)), -127.f), 127.f);
        q.z = (char)(int)fminf(fmaxf(rintf(__fdiv_rn(v.z, s)), -127.f), 127.f);
        q.w = (char)(int)fminf(fmaxf(rintf(__fdiv_rn(v.w, s)), -127.f), 127.f);
        reinterpret_cast<char4*>(g_Aq + (size_t)m * K_DIM + kb * 128)[lane] = q;
        if (lane == 0) g_xs[(size_t)m * KB + kb] = s;
    }
}

// ---------------------------------------------------------------------------
// Kernel 2: int8 GEMM, v4. CTA 64x128, 256 thr, 2 CTAs/SM, 4-stage cp.async,
// 128B chunks (= scale block), SW128 + ldmatrix.x4, exact s32 -> fp32 rescale.
// ---------------------------------------------------------------------------
__device__ __forceinline__ void load_chunk(uint32_t sbase, int stage, int c,
                                           int m0, int n0, int tid) {
    uint32_t sa = sbase + OFF_STG + stage * STAGE_BYTES;
    uint32_t sb = sa + A_STAGE;
    const int8_t* Ab = g_Aq + (size_t)m0 * K_DIM + c * BKB;
    const int8_t* Bb = g_Wq + (size_t)n0 * K_DIM + c * BKB;
    #pragma unroll
    for (int i = 0; i < 2; i++) {          // A: 64 rows * 8 segs = 512 ops
        int s = tid + i * 256;
        int row = s >> 3, seg = s & 7;
        cp_async16(sa + SWZ128(row * BKB + seg * 16),
                   Ab + (size_t)row * K_DIM + seg * 16);
    }
    #pragma unroll
    for (int i = 0; i < 4; i++) {          // B: 128 rows * 8 segs = 1024 ops
        int s = tid + i * 256;
        int row = s >> 3, seg = s & 7;
        cp_async16(sb + SWZ128(row * BKB + seg * 16),
                   Bb + (size_t)row * K_DIM + seg * 16);
    }
    asm volatile("cp.async.commit_group;");
}

__global__ void __launch_bounds__(256, 2) gemm_kernel(const float* __restrict__ ws,
                                                      const float* __restrict__ bias,
                                                      float* __restrict__ out) {
    extern __shared__ __align__(1024) char smem[];
    const uint32_t sbase = smem_u32(smem);
    const int tid = threadIdx.x;
    const int wid = tid >> 5;
    const int lid = tid & 31;
    const int g   = lid >> 2;
    const int t4  = lid & 3;
    const int n0 = blockIdx.x * BN;
    const int m0 = blockIdx.y * BM;
    const int mbase = (wid >> 2) * 32;     // 2 m-warps
    const int nbase = (wid & 3) * 32;      // 4 n-warps

    float* xs_s = reinterpret_cast<float*>(smem + OFF_XS);
    float* ws_s = reinterpret_cast<float*>(smem + OFF_WS);

    const int lrow = (lid & 7) + ((lid >> 3) & 1) * 8;
    const int lcol = (lid >> 4) * 16;

    for (int i = tid; i < BM * KB; i += 256) {
        int r = i >> 5, cb = i & 31;
        xs_s[r * XS_STRIDE + cb] = g_xs[(size_t)(m0 + r) * KB + cb];
    }
    if (tid < KB) ws_s[tid] = ws[(size_t)blockIdx.x * KB + tid];

    // prologue: prefetch chunks 0,1,2
    load_chunk(sbase, 0, 0, m0, n0, tid);
    load_chunk(sbase, 1, 1, m0, n0, tid);
    load_chunk(sbase, 2, 2, m0, n0, tid);
    __syncthreads();

    float facc[2][4][4] = {};

    int stage = 0;
    for (int c = 0; c < NCH; c++) {
        if (c < NCH - 2)       asm volatile("cp.async.wait_group 2;");
        else if (c == NCH - 2) asm volatile("cp.async.wait_group 1;");
        else                   asm volatile("cp.async.wait_group 0;");
        __syncthreads();

        if (c + 3 < NCH) {
            int ls = stage + 3; if (ls >= STAGES) ls -= STAGES;
            load_chunk(sbase, ls, c + 3, m0, n0, tid);
        }

        const uint32_t sa = sbase + OFF_STG + stage * STAGE_BYTES;
        const uint32_t sb = sa + A_STAGE;

        int32_t iacc[2][4][4];
        #pragma unroll
        for (int ks = 0; ks < 4; ks++) {
            const int k0 = ks * 32;
            uint32_t a[2][4], bb[2][4];
            #pragma unroll
            for (int mi = 0; mi < 2; mi++) {
                int r = mbase + mi * 16 + lrow;
                ldsm4(a[mi][0], a[mi][1], a[mi][2], a[mi][3],
                      sa + SWZ128((uint32_t)(r * BKB) + k0 + lcol));
            }
            #pragma unroll
            for (int nj = 0; nj < 2; nj++) {
                int r = nbase + nj * 16 + lrow;
                ldsm4(bb[nj][0], bb[nj][1], bb[nj][2], bb[nj][3],
                      sb + SWZ128((uint32_t)(r * BKB) + k0 + lcol));
            }
            #pragma unroll
            for (int mi = 0; mi < 2; mi++)
                #pragma unroll
                for (int ni = 0; ni < 4; ni++) {
                    int nj = ni >> 1, w = ni & 1;
                    if (ks == 0)
                        mma_s8_zc(iacc[mi][ni], a[mi], bb[nj][w], bb[nj][w + 2]);
                    else
                        mma_s8(iacc[mi][ni], a[mi], bb[nj][w], bb[nj][w + 2]);
                }
        }

        // chunk == one 128-K scale block: rescale exact s32 into fp32
        const float wsb = ws_s[c];
        #pragma unroll
        for (int mi = 0; mi < 2; mi++) {
            int r0 = mbase + mi * 16 + g;
            float s0 = xs_s[r0 * XS_STRIDE + c] * wsb;
            float s1 = xs_s[(r0 + 8) * XS_STRIDE + c] * wsb;
            #pragma unroll
            for (int ni = 0; ni < 4; ni++) {
                facc[mi][ni][0] += s0 * (float)iacc[mi][ni][0];
                facc[mi][ni][1] += s0 * (float)iacc[mi][ni][1];
                facc[mi][ni][2] += s1 * (float)iacc[mi][ni][2];
                facc[mi][ni][3] += s1 * (float)iacc[mi][ni][3];
            }
        }

        stage++; if (stage >= STAGES) stage = 0;
    }

    // epilogue: bias add, direct float2 stores; C frag rows g/g+8, cols 2*t4
    #pragma unroll
    for (int mi = 0; mi < 2; mi++) {
        int r0 = m0 + mbase + mi * 16 + g;
        #pragma unroll
        for (int ni = 0; ni < 4; ni++) {
            int c0 = n0 + nbase + ni * 8 + t4 * 2;
            float b0 = __ldg(bias + c0), b1 = __ldg(bias + c0 + 1);
            float2 v0 = make_float2(facc[mi][ni][0] + b0, facc[mi][ni][1] + b1);
            float2 v1 = make_float2(facc[mi][ni][2] + b0, facc[mi][ni][3] + b1);
            *reinterpret_cast<float2*>(out + (size_t)r0 * N_DIM + c0) = v0;
            *reinterpret_cast<float2*>(out + (size_t)(r0 + 8) * N_DIM + c0) = v1;
        }
    }
}

// ---------------------------------------------------------------------------
// Launch
// ---------------------------------------------------------------------------
extern "C" void kernel_launch(void* const* d_in, const int* in_sizes, int n_in,
                              void* d_out, int out_size) {
    const float* x    = (const float*)d_in[0];
    const void*  wraw = d_in[1];                 // int8 OR promoted int32/float32
    const float* ws   = (const float*)d_in[2];
    const float* bias = (const float*)d_in[3];
    float* out = (float*)d_out;

    cudaFuncSetAttribute(gemm_kernel, cudaFuncAttributeMaxDynamicSharedMemorySize,
                         SMEM_BYTES);

    prep_kernel<<<WBLK + XBLK, 256>>>((const uint32_t*)wraw, x);

    dim3 grid(N_DIM / BN, M_DIM / BM);   // 32 x 32 = 1024 CTAs
    gemm_kernel<<<grid, 256, SMEM_BYTES>>>(ws, bias, out);
}